// round 6
// baseline (speedup 1.0000x reference)
#include <cuda_runtime.h>

// Problem constants (from reference setup_inputs)
#define NB 8
#define NC 64
#define HH 128
#define WW 128
#define EH 64
#define EW 64
#define THETA 10.0f

#define CSPB 8                         // channels per block (apply kernel)
#define NCGRP (NC / CSPB)              // 8 channel groups
#define ROWS_PER_BLK 4                 // 4 warps -> 4 rows
#define HALO_ROWS (ROWS_PER_BLK + 2)   // 6 staged rows
#define NROWBLK (HH / ROWS_PER_BLK)    // 32
#define TBLK (ROWS_PER_BLK * 32)       // 128 threads

// Precomputed normalized weights: [n][y][k][x], k = 0..8 tap index.
// 8*128*9*128 floats = 4.72 MB (static device scratch; no runtime alloc).
__device__ float g_wbuf[NB * HH * 9 * WW];

// ---------------------------------------------------------------------------
// Kernel 1: per-pixel softmax weights from bilinear-upsampled edge.
// Boundary zero-padding of the MASK taps is folded into the stored weights.
// ---------------------------------------------------------------------------
__global__ __launch_bounds__(TBLK)
void geg_weights_kernel(const float* __restrict__ edge)
{
    const int t    = threadIdx.x;
    const int warp = t >> 5;
    const int lane = t & 31;
    const int y    = blockIdx.x * ROWS_PER_BLK + warp;  // 0..127
    const int n    = blockIdx.y;                        // 0..7
    const int x0   = lane * 4;

    const float* eptr = edge + (size_t)n * (EH * EW);
    const float sc = 63.0f / 127.0f;   // (EH-1)/(HH-1), align_corners

    float er[3][6];
    #pragma unroll
    for (int r = 0; r < 3; r++) {
        const int gy = y - 1 + r;
        float4 ev = make_float4(0.f, 0.f, 0.f, 0.f);
        if (gy >= 0 && gy < HH) {
            const float ys = (float)gy * sc;
            const int   yi = (int)ys;
            const float wy = ys - (float)yi;
            const int   y1 = min(yi + 1, EH - 1);
            const float* r0 = eptr + yi * EW;
            const float* r1 = eptr + y1 * EW;
            float v[4];
            #pragma unroll
            for (int p = 0; p < 4; p++) {
                const int   gx = x0 + p;
                const float xs = (float)gx * sc;
                const int   xi = (int)xs;
                const float wx = xs - (float)xi;
                const int   x1 = min(xi + 1, EW - 1);
                const float a  = r0[xi];
                const float b  = r0[x1];
                const float c0 = r1[xi];
                const float d  = r1[x1];
                const float top = a  + (b  - a ) * wx;
                const float bot = c0 + (d  - c0) * wx;
                v[p] = top + (bot - top) * wy;
            }
            ev = make_float4(v[0], v[1], v[2], v[3]);
        }
        float left  = __shfl_up_sync(0xffffffffu, ev.w, 1);
        float right = __shfl_down_sync(0xffffffffu, ev.x, 1);
        if (lane == 0)  left  = 0.f;
        if (lane == 31) right = 0.f;
        er[r][0] = left; er[r][1] = ev.x; er[r][2] = ev.y;
        er[r][3] = ev.z; er[r][4] = ev.w; er[r][5] = right;
    }

    float w[4][9];
    #pragma unroll
    for (int p = 0; p < 4; p++) {
        const float ec = er[1][p + 1];
        float s = 0.f;
        #pragma unroll
        for (int k = 0; k < 9; k++) {
            const float d  = ec - er[k / 3][p + (k % 3)];
            const float pw = __expf(-THETA * d * d);
            w[p][k] = pw;
            s += pw;
        }
        const float rs = 1.f / s;
        #pragma unroll
        for (int k = 0; k < 9; k++) w[p][k] *= rs;
    }

    if (y == 0) {
        #pragma unroll
        for (int p = 0; p < 4; p++) { w[p][0] = 0.f; w[p][1] = 0.f; w[p][2] = 0.f; }
    }
    if (y == HH - 1) {
        #pragma unroll
        for (int p = 0; p < 4; p++) { w[p][6] = 0.f; w[p][7] = 0.f; w[p][8] = 0.f; }
    }
    if (lane == 0)  { w[0][0] = 0.f; w[0][3] = 0.f; w[0][6] = 0.f; }
    if (lane == 31) { w[3][2] = 0.f; w[3][5] = 0.f; w[3][8] = 0.f; }

    float* wb = g_wbuf + ((size_t)(n * HH + y) * 9) * WW + x0;
    #pragma unroll
    for (int k = 0; k < 9; k++)
        *reinterpret_cast<float4*>(wb + (size_t)k * WW) =
            make_float4(w[0][k], w[1][k], w[2][k], w[3][k]);
}

// ---------------------------------------------------------------------------
// Kernel 2: apply weights across channels. Block stages a 6-row halo tile in
// double-buffered smem (one barrier per channel); prefetch for channel c+1 is
// in flight across the barrier + compute of channel c. Global loads per
// output pixel drop from 3 to 1.25 float4.
// ---------------------------------------------------------------------------
__global__ __launch_bounds__(TBLK, 6)
void geg_apply_kernel(const float* __restrict__ mask,
                      float* __restrict__ out)
{
    __shared__ float4 sbuf[2][HALO_ROWS * 32];   // 2 x 3 KB

    const int t    = threadIdx.x;
    const int warp = t >> 5;
    const int lane = t & 31;

    const int rowblk = blockIdx.x;     // 0..31
    const int cgrp   = blockIdx.y;     // 0..7
    const int n      = blockIdx.z;     // 0..7

    const int y0 = rowblk * ROWS_PER_BLK;
    const int y  = y0 + warp;
    const int x0 = lane * 4;

    const size_t img = (size_t)HH * WW;
    const float* mp = mask + ((size_t)n * NC + (size_t)cgrp * CSPB) * img;
    float*       op = out  + ((size_t)n * NC + (size_t)cgrp * CSPB) * img;

    // Staging slot assignment: slot s (0..191) -> tile row s>>5, col4 s&31.
    // Thread t owns slot t; threads t<64 also own slot 128+t (rows 4,5).
    const bool has2 = (t < 64);
    const int  gya  = min(max(y0 - 1 + (t >> 5), 0), HH - 1);
    const int  offA = gya * WW + lane * 4;
    const int  r1   = 4 + (t >> 5);                       // valid when has2
    const int  gyb  = min(max(y0 - 1 + r1, 0), HH - 1);
    const int  offB = gyb * WW + (t & 31) * 4;

    // Prologue: loads for channel 0 in flight while weights are fetched.
    float4 pa = *reinterpret_cast<const float4*>(mp + offA);
    float4 pb = make_float4(0.f, 0.f, 0.f, 0.f);
    if (has2) pb = *reinterpret_cast<const float4*>(mp + offB);

    // Load the 36 precomputed weights (9 coalesced float4 loads).
    float w[4][9];
    {
        const float* wb = g_wbuf + ((size_t)(n * HH + y) * 9) * WW + x0;
        #pragma unroll
        for (int k = 0; k < 9; k++) {
            float4 v = *reinterpret_cast<const float4*>(wb + (size_t)k * WW);
            w[0][k] = v.x; w[1][k] = v.y; w[2][k] = v.z; w[3][k] = v.w;
        }
    }

    const int offs = y * WW + x0;

    #pragma unroll
    for (int c = 0; c < CSPB; c++) {
        float4* buf = sbuf[c & 1];

        // Stage current channel's tile.
        buf[t] = pa;
        if (has2) buf[128 + t] = pb;

        // Issue next channel's global loads BEFORE the barrier: they complete
        // during barrier + compute of this channel.
        if (c < CSPB - 1) {
            const float* np = mp + img;
            pa = *reinterpret_cast<const float4*>(np + offA);
            if (has2) pb = *reinterpret_cast<const float4*>(np + offB);
        }

        __syncthreads();

        // Warp w reads tile rows w, w+1, w+2 (LDS.128, conflict-free).
        float4 m0 = buf[(warp + 0) * 32 + lane];
        float4 m1 = buf[(warp + 1) * 32 + lane];
        float4 m2 = buf[(warp + 2) * 32 + lane];

        float mr[3][6];
        {
            float l0 = __shfl_up_sync(0xffffffffu, m0.w, 1);
            float r0 = __shfl_down_sync(0xffffffffu, m0.x, 1);
            float l1 = __shfl_up_sync(0xffffffffu, m1.w, 1);
            float r1s = __shfl_down_sync(0xffffffffu, m1.x, 1);
            float l2 = __shfl_up_sync(0xffffffffu, m2.w, 1);
            float r2 = __shfl_down_sync(0xffffffffu, m2.x, 1);
            mr[0][0]=l0; mr[0][1]=m0.x; mr[0][2]=m0.y; mr[0][3]=m0.z; mr[0][4]=m0.w; mr[0][5]=r0;
            mr[1][0]=l1; mr[1][1]=m1.x; mr[1][2]=m1.y; mr[1][3]=m1.z; mr[1][4]=m1.w; mr[1][5]=r1s;
            mr[2][0]=l2; mr[2][1]=m2.x; mr[2][2]=m2.y; mr[2][3]=m2.z; mr[2][4]=m2.w; mr[2][5]=r2;
        }

        float a[4];
        #pragma unroll
        for (int p = 0; p < 4; p++) {
            float s = 0.f;
            #pragma unroll
            for (int k = 0; k < 9; k++)
                s = fmaf(w[p][k], mr[k / 3][p + (k % 3)], s);
            a[p] = s;
        }

        *reinterpret_cast<float4*>(op + offs) = make_float4(a[0], a[1], a[2], a[3]);

        mp += img;
        op += img;
    }
}

extern "C" void kernel_launch(void* const* d_in, const int* in_sizes, int n_in,
                              void* d_out, int out_size)
{
    const float* mask = (const float*)d_in[0];
    const float* edge = (const float*)d_in[1];
    if (n_in >= 2 && in_sizes[0] < in_sizes[1]) {   // defensive swap by size
        const float* tmp = mask; mask = edge; edge = tmp;
    }
    float* out = (float*)d_out;

    dim3 wgrid(NROWBLK, NB);            // 32 x 8 = 256 blocks
    geg_weights_kernel<<<wgrid, TBLK>>>(edge);

    dim3 agrid(NROWBLK, NCGRP, NB);     // 32 x 8 x 8 = 2048 blocks
    geg_apply_kernel<<<agrid, TBLK>>>(mask, out);
}